// round 7
// baseline (speedup 1.0000x reference)
#include <cuda_runtime.h>
#include <math.h>

#define H 256
#define W 256
#define V 192
#define D 256
#define S 256
#define HW (H*W)
#define PW 264              /* padded stride: data at [2,257], reads in [0,259] */

#define SQRT2_D 1.4142135623730951
#define DPf     ((float)(2.0 * SQRT2_D * 128.0 / 255.0))   /* sample spacing, px */
#define OFFf    ((float)(-SQRT2_D * 128.0))
#define INV_DPf ((float)(255.0 / (256.0 * SQRT2_D)))
#define DTf     ((float)(2.0 * SQRT2_D / 256.0))
#define PI_D    3.141592653589793

__device__ float2 g_imgP [PW * PW];  // padded (imgA,imgB), row-major
__device__ float2 g_imgTP[PW * PW];  // padded, transposed
__device__ float2 g_img2 [HW];       // unpadded interleave (for bwd final update)
__device__ float2 g_temp [V * D];    // residual sinogram, (A,B) interleaved
__device__ float4 g_trig4[V];        // {svDP, cvDP, svI, cvI} for bwd
__device__ float2 g_trigB[V];        // raw {cv, sv} for fwd

// ---------------------------------------------------------------------------
// prep: interleave both images into padded normal + padded transposed arrays
// (16x16 smem tiles, coalesced), zero the 2-cell border frame, trig tables.
// ---------------------------------------------------------------------------
__global__ void __launch_bounds__(256) prep_kernel(const float* __restrict__ img) {
    __shared__ float2 tile[16][17];
    const int tid = threadIdx.x;
    const int tx = tid & 15, ty = tid >> 4;
    const int bx = (blockIdx.x & 15) << 4;
    const int by = (blockIdx.x >> 4) << 4;

    {
        int x = bx + tx, y = by + ty;
        int p = y * W + x;
        float2 val = make_float2(img[p], img[p + HW]);
        g_img2[p] = val;
        g_imgP[(y + 2) * PW + (x + 2)] = val;
        tile[ty][tx] = val;
    }

    // border frame zeroing: frame = [0,259]^2 minus [2,257]^2 (2064 cells/array)
    if (blockIdx.x < 2) {
        float2* dst = (blockIdx.x == 0) ? g_imgP : g_imgTP;
        for (int i = tid; i < 2064; i += 256) {
            int r, c;
            if (i < 1040) {                    // rows {0,1,258,259} x cols [0,259]
                int rr = i / 260;  c = i - rr * 260;
                r = (rr < 2) ? rr : (256 + rr);
            } else {                           // cols {0,1,258,259} x rows [2,257]
                int j = i - 1040;
                int cc = j / 256;  r = 2 + (j - cc * 256);
                c = (cc < 2) ? cc : (256 + cc);
            }
            dst[r * PW + c] = make_float2(0.f, 0.f);
        }
    }

    // trig tables (one thread per angle)
    if (blockIdx.x < V && tid == 0) {
        const int v = blockIdx.x;
        float cv, sv;
        float af = (float)((double)v * (PI_D / 192.0));
        sincosf(af, &sv, &cv);
        g_trigB[v] = make_float2(cv, sv);
        g_trig4[v] = make_float4(sv * DPf, cv * DPf, sv * INV_DPf, cv * INV_DPf);
    }

    __syncthreads();
    {
        int xo = bx + ty, yo = by + tx;
        g_imgTP[(xo + 2) * PW + (yo + 2)] = tile[tx][ty];
    }
}

// ---------------------------------------------------------------------------
// forward projection: ONE THREAD PER RAY (v,d). Loop over samples k.
// Padded image -> no bounds checks anywhere. Orientation chosen so the
// fast-varying coordinate ACROSS LANES (adjacent detectors) is contiguous.
// ---------------------------------------------------------------------------
__global__ void __launch_bounds__(128) fwd_kernel(const float* __restrict__ proj) {
    const int id = blockIdx.x * 128 + threadIdx.x;   // ray id
    const int v = id >> 8;
    const int d = id & 255;

    const float2 tv = g_trigB[v];
    const float cv = tv.x, sv = tv.y;
    const float s128 = fmaf((float)d, DPf, OFFf);

    // padded coords: bX/bY include +2 pad offset
    float bx0 = fmaf(OFFf, cv, fmaf(-s128, sv, 129.5f));   // x at k=0 (+2)
    float by0 = fmaf(OFFf, sv, fmaf( s128, cv, 129.5f));   // y at k=0 (+2)
    const float sx0 = DPf * cv, sy0 = DPf * sv;

    // across-lane step: x-mag = |sv|*DP, y-mag = |cv|*DP. Keep larger contiguous.
    const bool useN = fabsf(sv) >= fabsf(cv);
    const float2* __restrict__ im = useN ? g_imgP : g_imgTP;
    const float bX = useN ? bx0 : by0;
    const float bY = useN ? by0 : bx0;
    const float sX = useN ? sx0 : sy0;
    const float sY = useN ? sy0 : sx0;

    // per-thread k-range: X,Y in [0.8, 258.2]  (orig [-1.2,256.2], superset of
    // all samples with any nonzero corner; everything in range reads safely)
    float lo = 0.f, hi = 255.f;
    bool empty = false;
    {
        if (fabsf(sX) > 1e-7f) {
            float r = 1.0f / sX;
            float t1 = (0.8f - bX) * r, t2 = (258.2f - bX) * r;
            lo = fmaxf(lo, fminf(t1, t2)); hi = fminf(hi, fmaxf(t1, t2));
        } else if (bX < 0.8f || bX > 258.2f) empty = true;
        if (fabsf(sY) > 1e-7f) {
            float r = 1.0f / sY;
            float t1 = (0.8f - bY) * r, t2 = (258.2f - bY) * r;
            lo = fmaxf(lo, fminf(t1, t2)); hi = fminf(hi, fmaxf(t1, t2));
        } else if (bY < 0.8f || bY > 258.2f) empty = true;
    }
    int klo = (int)ceilf(lo), khi = (int)floorf(hi);
    if (empty) { klo = 1; khi = 0; }

    float sA = 0.f, sB = 0.f;
    #pragma unroll 4
    for (int k = klo; k <= khi; ++k) {
        float X = fmaf((float)k, sX, bX);
        float Y = fmaf((float)k, sY, bY);
        float Xf = floorf(X), Yf = floorf(Y);
        float fx = X - Xf,   fy = Y - Yf;
        int base = (int)Yf * PW + (int)Xf;
        float2 p00 = __ldg(im + base),      p10 = __ldg(im + base + 1);
        float2 p01 = __ldg(im + base + PW), p11 = __ldg(im + base + PW + 1);
        float gx = 1.f - fx, gy = 1.f - fy;
        float w00 = gx * gy, w10 = fx * gy, w01 = gx * fy, w11 = fx * fy;
        sA = fmaf(p00.x, w00, fmaf(p10.x, w10, fmaf(p01.x, w01, fmaf(p11.x, w11, sA))));
        sB = fmaf(p00.y, w00, fmaf(p10.y, w10, fmaf(p01.y, w01, fmaf(p11.y, w11, sB))));
    }

    g_temp[id] = make_float2(fmaf(DTf, sA, -__ldg(proj + id)),
                             fmaf(DTf, sB, -__ldg(proj + V * D + id)));
}

// ---------------------------------------------------------------------------
// backprojection + update, 90-degree angle pairing (exact regrouping):
//   v    : q0 = P00+P01 (det j0),      q1 = P10+P11 (det j0+1)
//   v+96 : r0 = P01+P11 (det 254-k0),  r1 = P00+P10 (det 255-k0)
// Dual accumulator chains to halve FMA dependency depth.
// ---------------------------------------------------------------------------
__global__ void __launch_bounds__(128) bwd_kernel(const float* __restrict__ wptr,
                                                  float* __restrict__ out) {
    __shared__ float4 sg[V / 2];
    const int tid = threadIdx.x;
    if (tid < V / 2) sg[tid] = g_trig4[tid];
    __syncthreads();

    const int p = blockIdx.x * 128 + tid;
    const int ix = p & (W - 1);
    const int iy = p >> 8;
    const float px = (float)ix - 127.5f;
    const float py = (float)iy - 127.5f;
    const float npx = -px;

    float accA0 = 0.f, accB0 = 0.f, accA1 = 0.f, accB1 = 0.f;
    const float2* __restrict__ row  = g_temp;             // angle v
    const float2* __restrict__ rowm = g_temp + 96 * D;    // angle v+96

    #pragma unroll 2
    for (int v = 0; v < V / 2; ++v, row += D, rowm += D) {
        const float4 q = sg[v];
        const float svDP = q.x, cvDP = q.y, svI = q.z, cvI = q.w;

        const float jc = fmaf(py, cvI, fmaf(npx, svI, 127.5f));
        const float kc = fmaf(px, cvI, fmaf(py,  svI, 127.5f));
        const float jf = floorf(jc), kf = floorf(kc);
        const float fj = jc - jf,    fk = kc - kf;
        const int   j0 = (int)jf;
        const int   k0 = (int)kf;

        const float dx00 = fmaf(fj, svDP, -(fk * cvDP));
        const float u    = fmaf(fj, cvDP,  (fk * svDP));
        const float dx10 = dx00 - svDP;
        const float dx01 = dx00 + cvDP;
        const float dx11 = dx10 + cvDP;
        const float e10  = u - cvDP;
        const float e01  = u - svDP;
        const float e11  = e10 - svDP;

        const float hx00 = __saturatef(1.f - fabsf(dx00));
        const float hx10 = __saturatef(1.f - fabsf(dx10));
        const float hx01 = __saturatef(1.f - fabsf(dx01));
        const float hx11 = __saturatef(1.f - fabsf(dx11));
        const float hy00 = __saturatef(1.f - fabsf(u));
        const float hy10 = __saturatef(1.f - fabsf(e10));
        const float hy01 = __saturatef(1.f - fabsf(e01));
        const float hy11 = __saturatef(1.f - fabsf(e11));

        const float P00 = hx00 * hy00;
        const float P10 = hx10 * hy10;
        const float P01 = hx01 * hy01;
        const float P11 = hx11 * hy11;

        const float q0 = P00 + P01, q1 = P10 + P11;   // angle v
        const float r0 = P01 + P11, r1 = P00 + P10;   // angle v+96

        const float2 t0 = __ldg(row + j0);
        const float2 t1 = __ldg(row + j0 + 1);
        const float2 m0 = __ldg(rowm + (254 - k0));
        const float2 m1 = __ldg(rowm + (255 - k0));
        accA0 = fmaf(t0.x, q0, fmaf(t1.x, q1, accA0));
        accB0 = fmaf(t0.y, q0, fmaf(t1.y, q1, accB0));
        accA1 = fmaf(m0.x, r0, fmaf(m1.x, r1, accA1));
        accB1 = fmaf(m0.y, r0, fmaf(m1.y, r1, accB1));
    }

    const float wdt = __ldg(wptr) * DTf;
    const float2 ia = g_img2[p];
    out[p]      = fmaf(-wdt, accA0 + accA1, ia.x);
    out[p + HW] = fmaf(-wdt, accB0 + accB1, ia.y);
}

// ---------------------------------------------------------------------------
extern "C" void kernel_launch(void* const* d_in, const int* in_sizes, int n_in,
                              void* d_out, int out_size) {
    const float* img  = (const float*)d_in[0];   // [2,1,256,256]
    const float* proj = (const float*)d_in[1];   // [2,1,192,256]
    const float* wptr = (const float*)d_in[2];   // [1]
    float* out = (float*)d_out;                  // [2,1,256,256]

    prep_kernel<<<256, 256>>>(img);
    fwd_kernel<<<(V * D) / 128, 128>>>(proj);
    bwd_kernel<<<HW / 128, 128>>>(wptr, out);
}

// round 8
// speedup vs baseline: 1.3515x; 1.3515x over previous
#include <cuda_runtime.h>
#include <math.h>

#define H 256
#define W 256
#define V 192
#define D 256
#define S 256
#define HW (H*W)
#define PW 264              /* padded stride: data at [2,257], frame zeros [0,259] */

#define SQRT2_D 1.4142135623730951
#define DPf     ((float)(2.0 * SQRT2_D * 128.0 / 255.0))   /* sample spacing, px */
#define OFFf    ((float)(-SQRT2_D * 128.0))
#define INV_DPf ((float)(255.0 / (256.0 * SQRT2_D)))
#define DTf     ((float)(2.0 * SQRT2_D / 256.0))
#define PI_D    3.141592653589793

__device__ float2 g_imgP [PW * PW];  // padded (imgA,imgB), row-major
__device__ float2 g_imgTP[PW * PW];  // padded, transposed
__device__ float2 g_img2 [HW];       // unpadded interleave (bwd final update)
__device__ float2 g_temp [V * D];    // residual sinogram rows v<96 (A,B)
__device__ float4 g_pair [V * D];    // (temp[j], temp[j+1]) x both images
__device__ float  g_colA [8 * 96 * 256];  // column partial sums, 8 row-groups
__device__ float  g_colB [8 * 96 * 256];
__device__ float4 g_trig4[96];       // {svDP, cvDP, svI, cvI} for bwd
__device__ float2 g_trigB[96];       // raw {cv, sv} for fwd2

// ---------------------------------------------------------------------------
// prep: padded normal + padded transposed interleaved images (coalesced via
// smem tiles), border-frame zeroing, trig tables.
// ---------------------------------------------------------------------------
__global__ void __launch_bounds__(256) prep_kernel(const float* __restrict__ img) {
    __shared__ float2 tile[16][17];
    const int tid = threadIdx.x;
    const int tx = tid & 15, ty = tid >> 4;
    const int bx = (blockIdx.x & 15) << 4;
    const int by = (blockIdx.x >> 4) << 4;

    {
        int x = bx + tx, y = by + ty;
        int p = y * W + x;
        float2 val = make_float2(img[p], img[p + HW]);
        g_img2[p] = val;
        g_imgP[(y + 2) * PW + (x + 2)] = val;
        tile[ty][tx] = val;
    }

    // border frame zeroing: [0,259]^2 minus [2,257]^2 = 2064 cells per array
    if (blockIdx.x < 2) {
        float2* dst = (blockIdx.x == 0) ? g_imgP : g_imgTP;
        for (int i = tid; i < 2064; i += 256) {
            int r, c;
            if (i < 1040) {                    // rows {0,1,258,259} x cols [0,259]
                int rr = i / 260;  c = i - rr * 260;
                r = (rr < 2) ? rr : (256 + rr);
            } else {                           // cols {0,1,258,259} x rows [2,257]
                int j = i - 1040;
                int cc = j / 256;  r = 2 + (j - cc * 256);
                c = (cc < 2) ? cc : (256 + cc);
            }
            dst[r * PW + c] = make_float2(0.f, 0.f);
        }
    }

    if (blockIdx.x < 96 && tid == 0) {
        const int v = blockIdx.x;
        float cv, sv;
        float af = (float)((double)v * (PI_D / 192.0));
        sincosf(af, &sv, &cv);
        g_trigB[v] = make_float2(cv, sv);
        g_trig4[v] = make_float4(sv * DPf, cv * DPf, sv * INV_DPf, cv * INV_DPf);
    }

    __syncthreads();
    {
        int xo = bx + ty, yo = by + tx;
        g_imgTP[(xo + 2) * PW + (yo + 2)] = tile[tx][ty];
    }
}

// ---------------------------------------------------------------------------
// fwd2: sample field F_v[j][k] for base angles v<96 serves BOTH sinogram
// halves (90-degree identity): row-sum_k -> sino[v][j]; col-sum_j -> the
// reversed row sino[v+96]. Warp-per-row (lanes along k), padded images,
// chunk-aligned k loop so per-lane column accumulators stay in registers.
// 768 blocks = 96 angles x 8 groups of 32 rows. Deterministic reductions.
// ---------------------------------------------------------------------------
__global__ void __launch_bounds__(256) fwd2_kernel(const float* __restrict__ proj) {
    __shared__ float2 shW[8][256];               // per-warp column partials
    const int bid = blockIdx.x;
    const int v   = bid >> 3;
    const int grp = bid & 7;
    const int tid = threadIdx.x;
    const int warp = tid >> 5, lane = tid & 31;

    const float2 tv = g_trigB[v];
    const float cv = tv.x, sv = tv.y;
    const bool steep = fabsf(sv) > fabsf(cv);
    const float2* __restrict__ im = steep ? g_imgTP : g_imgP;
    const float c2 = steep ? sv : cv;
    const float s2 = steep ? cv : sv;

    float cA[8], cB[8];
    #pragma unroll
    for (int c = 0; c < 8; ++c) { cA[c] = 0.f; cB[c] = 0.f; }

    #pragma unroll 1
    for (int r = 0; r < 4; ++r) {
        const int j = (grp << 5) + (r << 3) + warp;
        const float s128 = fmaf((float)j, DPf, OFFf);
        const float ax0 = fmaf(-s128, sv, 129.5f);   // padded (+2)
        const float ay0 = fmaf( s128, cv, 129.5f);
        const float aX = steep ? ay0 : ax0;
        const float aY = steep ? ax0 : ay0;
        const float bX = fmaf(OFFf, c2, aX), sX = DPf * c2;   // X(k) = bX + k*sX
        const float bY = fmaf(OFFf, s2, aY), sY = DPf * s2;

        // warp-uniform k-range: padded coords in [0.999, 258.001] (superset of
        // all samples with any nonzero corner; |sX| >= DP/sqrt2 > 1, never 0)
        float lo = 0.f, hi = 255.f;
        bool empty = false;
        {
            float rr = 1.0f / sX;
            float t1 = (0.999f - bX) * rr, t2 = (258.001f - bX) * rr;
            lo = fmaxf(lo, fminf(t1, t2)); hi = fminf(hi, fmaxf(t1, t2));
        }
        if (fabsf(sY) > 1e-6f) {
            float rr = 1.0f / sY;
            float t1 = (0.999f - bY) * rr, t2 = (258.001f - bY) * rr;
            lo = fmaxf(lo, fminf(t1, t2)); hi = fminf(hi, fmaxf(t1, t2));
        } else if (bY < 0.999f || bY > 258.001f) empty = true;

        int klo = (int)ceilf(lo), khi = (int)floorf(hi);
        float rowA = 0.f, rowB = 0.f;
        if (!empty && klo <= khi) {
            const int c0 = klo >> 5, c1 = khi >> 5;
            #pragma unroll
            for (int c = 0; c < 8; ++c) {
                if (c >= c0 && c <= c1) {           // warp-uniform branch
                    const int k = (c << 5) + lane;
                    const float pred = (k >= klo && k <= khi) ? 1.f : 0.f;
                    float X = fmaf((float)k, sX, bX);
                    float Y = fmaf((float)k, sY, bY);
                    X = fminf(fmaxf(X, 0.f), 258.f);   // safe for pred=0 lanes
                    Y = fminf(fmaxf(Y, 0.f), 258.f);
                    float Xf = floorf(X), Yf = floorf(Y);
                    float fx = X - Xf, fy = Y - Yf;
                    int base = (int)Yf * PW + (int)Xf;
                    float2 p00 = __ldg(im + base),      p10 = __ldg(im + base + 1);
                    float2 p01 = __ldg(im + base + PW), p11 = __ldg(im + base + PW + 1);
                    float gx = 1.f - fx, gy = 1.f - fy;
                    float w00 = gx * gy, w10 = fx * gy, w01 = gx * fy, w11 = fx * fy;
                    float fa = fmaf(p00.x, w00, fmaf(p10.x, w10, fmaf(p01.x, w01, p11.x * w11)));
                    float fb = fmaf(p00.y, w00, fmaf(p10.y, w10, fmaf(p01.y, w01, p11.y * w11)));
                    fa *= pred; fb *= pred;
                    rowA += fa;  rowB += fb;
                    cA[c] += fa; cB[c] += fb;
                }
            }
        }
        #pragma unroll
        for (int o = 16; o; o >>= 1) {
            rowA += __shfl_xor_sync(0xffffffffu, rowA, o);
            rowB += __shfl_xor_sync(0xffffffffu, rowB, o);
        }
        if (lane == 0) {
            int idx = v * D + j;
            g_temp[idx] = make_float2(fmaf(DTf, rowA, -__ldg(proj + idx)),
                                      fmaf(DTf, rowB, -__ldg(proj + idx + V * D)));
        }
    }

    // deterministic column reduction: warp slices -> smem -> fixed-order sum
    #pragma unroll
    for (int c = 0; c < 8; ++c)
        shW[warp][(c << 5) + lane] = make_float2(cA[c], cB[c]);
    __syncthreads();
    float a = 0.f, b = 0.f;
    #pragma unroll
    for (int w = 0; w < 8; ++w) {
        float2 t = shW[w][tid];
        a += t.x; b += t.y;
    }
    g_colA[((grp * 96 + v) << 8) + tid] = a;
    g_colB[((grp * 96 + v) << 8) + tid] = b;
}

// ---------------------------------------------------------------------------
// combine: finalize sinogram rows v>=96 from column slices (fixed-order sum,
// deterministic), and build the float4 pair array (t[j], t[j+1]) for bwd.
// ---------------------------------------------------------------------------
__global__ void __launch_bounds__(256) combine_kernel(const float* __restrict__ proj) {
    __shared__ float2 sval[256];
    const int v = blockIdx.x;          // 0..191
    const int j = threadIdx.x;
    float2 val;
    if (v < 96) {
        val = g_temp[v * D + j];
    } else {
        const int vb = v - 96;
        const int kk = 255 - j;
        float a = 0.f, b = 0.f;
        #pragma unroll
        for (int g = 0; g < 8; ++g) {
            a += g_colA[((g * 96 + vb) << 8) + kk];
            b += g_colB[((g * 96 + vb) << 8) + kk];
        }
        int idx = v * D + j;
        val = make_float2(fmaf(DTf, a, -__ldg(proj + idx)),
                          fmaf(DTf, b, -__ldg(proj + idx + V * D)));
    }
    sval[j] = val;
    __syncthreads();
    float2 nxt = sval[min(j + 1, 255)];
    g_pair[(v << 8) + j] = make_float4(val.x, val.y, nxt.x, nxt.y);
}

// ---------------------------------------------------------------------------
// backprojection + update, 90-degree angle pairing; pair loads (LDG.128):
//   v    : q0 -> det j0,      q1 -> det j0+1        (one float4)
//   v+96 : r0 -> det 254-k0,  r1 -> det 255-k0      (one float4)
// ---------------------------------------------------------------------------
__global__ void __launch_bounds__(128) bwd_kernel(const float* __restrict__ wptr,
                                                  float* __restrict__ out) {
    __shared__ float4 sg[96];
    const int tid = threadIdx.x;
    if (tid < 96) sg[tid] = g_trig4[tid];
    __syncthreads();

    const int p = blockIdx.x * 128 + tid;
    const int ix = p & (W - 1);
    const int iy = p >> 8;
    const float px = (float)ix - 127.5f;
    const float py = (float)iy - 127.5f;
    const float npx = -px;

    float accA0 = 0.f, accB0 = 0.f, accA1 = 0.f, accB1 = 0.f;
    const float4* __restrict__ row  = g_pair;            // angle v
    const float4* __restrict__ rowm = g_pair + 96 * D;   // angle v+96

    #pragma unroll 2
    for (int v = 0; v < 96; ++v, row += D, rowm += D) {
        const float4 q = sg[v];
        const float svDP = q.x, cvDP = q.y, svI = q.z, cvI = q.w;

        const float jc = fmaf(py, cvI, fmaf(npx, svI, 127.5f));
        const float kc = fmaf(px, cvI, fmaf(py,  svI, 127.5f));
        const float jf = floorf(jc), kf = floorf(kc);
        const float fj = jc - jf,    fk = kc - kf;
        const int   j0 = (int)jf;
        const int   k0 = (int)kf;

        const float dx00 = fmaf(fj, svDP, -(fk * cvDP));
        const float u    = fmaf(fj, cvDP,  (fk * svDP));
        const float dx10 = dx00 - svDP;
        const float dx01 = dx00 + cvDP;
        const float dx11 = dx10 + cvDP;
        const float e10  = u - cvDP;
        const float e01  = u - svDP;
        const float e11  = e10 - svDP;

        const float hx00 = __saturatef(1.f - fabsf(dx00));
        const float hx10 = __saturatef(1.f - fabsf(dx10));
        const float hx01 = __saturatef(1.f - fabsf(dx01));
        const float hx11 = __saturatef(1.f - fabsf(dx11));
        const float hy00 = __saturatef(1.f - fabsf(u));
        const float hy10 = __saturatef(1.f - fabsf(e10));
        const float hy01 = __saturatef(1.f - fabsf(e01));
        const float hy11 = __saturatef(1.f - fabsf(e11));

        const float P00 = hx00 * hy00;
        const float P10 = hx10 * hy10;
        const float P01 = hx01 * hy01;
        const float P11 = hx11 * hy11;

        const float q0 = P00 + P01, q1 = P10 + P11;   // angle v
        const float r0 = P01 + P11, r1 = P00 + P10;   // angle v+96

        const float4 t01 = __ldg(row + j0);
        const float4 m01 = __ldg(rowm + (254 - k0));
        accA0 = fmaf(t01.x, q0, fmaf(t01.z, q1, accA0));
        accB0 = fmaf(t01.y, q0, fmaf(t01.w, q1, accB0));
        accA1 = fmaf(m01.x, r0, fmaf(m01.z, r1, accA1));
        accB1 = fmaf(m01.y, r0, fmaf(m01.w, r1, accB1));
    }

    const float wdt = __ldg(wptr) * DTf;
    const float2 ia = g_img2[p];
    out[p]      = fmaf(-wdt, accA0 + accA1, ia.x);
    out[p + HW] = fmaf(-wdt, accB0 + accB1, ia.y);
}

// ---------------------------------------------------------------------------
extern "C" void kernel_launch(void* const* d_in, const int* in_sizes, int n_in,
                              void* d_out, int out_size) {
    const float* img  = (const float*)d_in[0];   // [2,1,256,256]
    const float* proj = (const float*)d_in[1];   // [2,1,192,256]
    const float* wptr = (const float*)d_in[2];   // [1]
    float* out = (float*)d_out;                  // [2,1,256,256]

    prep_kernel<<<256, 256>>>(img);
    fwd2_kernel<<<768, 256>>>(proj);
    combine_kernel<<<192, 256>>>(proj);
    bwd_kernel<<<HW / 128, 128>>>(wptr, out);
}

// round 9
// speedup vs baseline: 1.6099x; 1.1912x over previous
#include <cuda_runtime.h>
#include <math.h>

#define H 256
#define W 256
#define V 192
#define D 256
#define S 256
#define HW (H*W)
#define PW 264              /* padded stride: data at [2,257], frame zeros [0,259] */

#define SQRT2_D 1.4142135623730951
#define DPf     ((float)(2.0 * SQRT2_D * 128.0 / 255.0))   /* sample spacing, px */
#define OFFf    ((float)(-SQRT2_D * 128.0))
#define INV_DPf ((float)(255.0 / (256.0 * SQRT2_D)))
#define DTf     ((float)(2.0 * SQRT2_D / 256.0))
#define PI_D    3.141592653589793

__device__ float2 g_imgP [PW * PW];  // padded (imgA,imgB), row-major
__device__ float2 g_imgTP[PW * PW];  // padded, transposed
__device__ float2 g_img2 [HW];       // unpadded interleave (bwd final update)
__device__ float2 g_temp [V * D];    // residual sinogram rows v<96 (A,B)
__device__ float4 g_pair [V * D];    // (temp[j], temp[j+1]) x both images
__device__ float  g_colA [8 * 96 * 256];  // column partial sums, 8 row-groups
__device__ float  g_colB [8 * 96 * 256];
__device__ float4 g_trig4[96];       // {svDP, cvDP, svI, cvI} for bwd
__device__ float2 g_trigB[96];       // raw {cv, sv} for fwd2

// ---------------------------------------------------------------------------
// prep: padded normal + padded transposed interleaved images (coalesced via
// smem tiles), border-frame zeroing, trig tables.
// ---------------------------------------------------------------------------
__global__ void __launch_bounds__(256) prep_kernel(const float* __restrict__ img) {
    __shared__ float2 tile[16][17];
    const int tid = threadIdx.x;
    const int tx = tid & 15, ty = tid >> 4;
    const int bx = (blockIdx.x & 15) << 4;
    const int by = (blockIdx.x >> 4) << 4;

    {
        int x = bx + tx, y = by + ty;
        int p = y * W + x;
        float2 val = make_float2(img[p], img[p + HW]);
        g_img2[p] = val;
        g_imgP[(y + 2) * PW + (x + 2)] = val;
        tile[ty][tx] = val;
    }

    // border frame zeroing: [0,259]^2 minus [2,257]^2 = 2064 cells per array
    if (blockIdx.x < 2) {
        float2* dst = (blockIdx.x == 0) ? g_imgP : g_imgTP;
        for (int i = tid; i < 2064; i += 256) {
            int r, c;
            if (i < 1040) {                    // rows {0,1,258,259} x cols [0,259]
                int rr = i / 260;  c = i - rr * 260;
                r = (rr < 2) ? rr : (256 + rr);
            } else {                           // cols {0,1,258,259} x rows [2,257]
                int j = i - 1040;
                int cc = j / 256;  r = 2 + (j - cc * 256);
                c = (cc < 2) ? cc : (256 + cc);
            }
            dst[r * PW + c] = make_float2(0.f, 0.f);
        }
    }

    if (blockIdx.x < 96 && tid == 0) {
        const int v = blockIdx.x;
        float cv, sv;
        float af = (float)((double)v * (PI_D / 192.0));
        sincosf(af, &sv, &cv);
        g_trigB[v] = make_float2(cv, sv);
        g_trig4[v] = make_float4(sv * DPf, cv * DPf, sv * INV_DPf, cv * INV_DPf);
    }

    __syncthreads();
    {
        int xo = bx + ty, yo = by + tx;
        g_imgTP[(xo + 2) * PW + (yo + 2)] = tile[tx][ty];
    }
}

// ---------------------------------------------------------------------------
// fwd2: sample field F_v[j][k] for base angles v<96 serves BOTH sinogram
// halves (90-degree identity): row-sum_k -> sino[v][j]; col-sum_j -> the
// reversed row sino[v+96]. Warp-per-row (lanes along k), padded images.
// ---------------------------------------------------------------------------
__global__ void __launch_bounds__(256) fwd2_kernel(const float* __restrict__ proj) {
    __shared__ float2 shW[8][256];               // per-warp column partials
    const int bid = blockIdx.x;
    const int v   = bid >> 3;
    const int grp = bid & 7;
    const int tid = threadIdx.x;
    const int warp = tid >> 5, lane = tid & 31;

    const float2 tv = g_trigB[v];
    const float cv = tv.x, sv = tv.y;
    const bool steep = fabsf(sv) > fabsf(cv);
    const float2* __restrict__ im = steep ? g_imgTP : g_imgP;
    const float c2 = steep ? sv : cv;
    const float s2 = steep ? cv : sv;

    float cA[8], cB[8];
    #pragma unroll
    for (int c = 0; c < 8; ++c) { cA[c] = 0.f; cB[c] = 0.f; }

    #pragma unroll 1
    for (int r = 0; r < 4; ++r) {
        const int j = (grp << 5) + (r << 3) + warp;
        const float s128 = fmaf((float)j, DPf, OFFf);
        const float ax0 = fmaf(-s128, sv, 129.5f);   // padded (+2)
        const float ay0 = fmaf( s128, cv, 129.5f);
        const float aX = steep ? ay0 : ax0;
        const float aY = steep ? ax0 : ay0;
        const float bX = fmaf(OFFf, c2, aX), sX = DPf * c2;   // X(k) = bX + k*sX
        const float bY = fmaf(OFFf, s2, aY), sY = DPf * s2;

        float lo = 0.f, hi = 255.f;
        bool empty = false;
        {
            float rr = 1.0f / sX;
            float t1 = (0.999f - bX) * rr, t2 = (258.001f - bX) * rr;
            lo = fmaxf(lo, fminf(t1, t2)); hi = fminf(hi, fmaxf(t1, t2));
        }
        if (fabsf(sY) > 1e-6f) {
            float rr = 1.0f / sY;
            float t1 = (0.999f - bY) * rr, t2 = (258.001f - bY) * rr;
            lo = fmaxf(lo, fminf(t1, t2)); hi = fminf(hi, fmaxf(t1, t2));
        } else if (bY < 0.999f || bY > 258.001f) empty = true;

        int klo = (int)ceilf(lo), khi = (int)floorf(hi);
        float rowA = 0.f, rowB = 0.f;
        if (!empty && klo <= khi) {
            const int c0 = klo >> 5, c1 = khi >> 5;
            #pragma unroll
            for (int c = 0; c < 8; ++c) {
                if (c >= c0 && c <= c1) {           // warp-uniform branch
                    const int k = (c << 5) + lane;
                    const float pred = (k >= klo && k <= khi) ? 1.f : 0.f;
                    float X = fmaf((float)k, sX, bX);
                    float Y = fmaf((float)k, sY, bY);
                    X = fminf(fmaxf(X, 0.f), 258.f);   // safe for pred=0 lanes
                    Y = fminf(fmaxf(Y, 0.f), 258.f);
                    float Xf = floorf(X), Yf = floorf(Y);
                    float fx = X - Xf, fy = Y - Yf;
                    int base = (int)Yf * PW + (int)Xf;
                    float2 p00 = __ldg(im + base),      p10 = __ldg(im + base + 1);
                    float2 p01 = __ldg(im + base + PW), p11 = __ldg(im + base + PW + 1);
                    float gx = 1.f - fx, gy = 1.f - fy;
                    float w00 = gx * gy, w10 = fx * gy, w01 = gx * fy, w11 = fx * fy;
                    float fa = fmaf(p00.x, w00, fmaf(p10.x, w10, fmaf(p01.x, w01, p11.x * w11)));
                    float fb = fmaf(p00.y, w00, fmaf(p10.y, w10, fmaf(p01.y, w01, p11.y * w11)));
                    fa *= pred; fb *= pred;
                    rowA += fa;  rowB += fb;
                    cA[c] += fa; cB[c] += fb;
                }
            }
        }
        #pragma unroll
        for (int o = 16; o; o >>= 1) {
            rowA += __shfl_xor_sync(0xffffffffu, rowA, o);
            rowB += __shfl_xor_sync(0xffffffffu, rowB, o);
        }
        if (lane == 0) {
            int idx = v * D + j;
            g_temp[idx] = make_float2(fmaf(DTf, rowA, -__ldg(proj + idx)),
                                      fmaf(DTf, rowB, -__ldg(proj + idx + V * D)));
        }
    }

    // deterministic column reduction: warp slices -> smem -> fixed-order sum
    #pragma unroll
    for (int c = 0; c < 8; ++c)
        shW[warp][(c << 5) + lane] = make_float2(cA[c], cB[c]);
    __syncthreads();
    float a = 0.f, b = 0.f;
    #pragma unroll
    for (int w = 0; w < 8; ++w) {
        float2 t = shW[w][tid];
        a += t.x; b += t.y;
    }
    g_colA[((grp * 96 + v) << 8) + tid] = a;
    g_colB[((grp * 96 + v) << 8) + tid] = b;
}

// ---------------------------------------------------------------------------
// combine: finalize sinogram rows v>=96 (fixed-order, deterministic) and
// build the float4 pair array (t[j], t[j+1]) for bwd.
// ---------------------------------------------------------------------------
__global__ void __launch_bounds__(256) combine_kernel(const float* __restrict__ proj) {
    __shared__ float2 sval[256];
    const int v = blockIdx.x;          // 0..191
    const int j = threadIdx.x;
    float2 val;
    if (v < 96) {
        val = g_temp[v * D + j];
    } else {
        const int vb = v - 96;
        const int kk = 255 - j;
        float a = 0.f, b = 0.f;
        #pragma unroll
        for (int g = 0; g < 8; ++g) {
            a += g_colA[((g * 96 + vb) << 8) + kk];
            b += g_colB[((g * 96 + vb) << 8) + kk];
        }
        int idx = v * D + j;
        val = make_float2(fmaf(DTf, a, -__ldg(proj + idx)),
                          fmaf(DTf, b, -__ldg(proj + idx + V * D)));
    }
    sval[j] = val;
    __syncthreads();
    float2 nxt = sval[min(j + 1, 255)];
    g_pair[(v << 8) + j] = make_float4(val.x, val.y, nxt.x, nxt.y);
}

// ---------------------------------------------------------------------------
// backprojection + update. 512-thread blocks: 4 angle-slices x 128 pixels.
// Each slice handles 24 angle-pairs (v, v+96) for the same 128 pixels;
// slices 1-3 publish partials to smem, slice 0 combines in FIXED order
// (deterministic) and writes the output. 4x the warps of the old layout.
// ---------------------------------------------------------------------------
__global__ void __launch_bounds__(512) bwd_kernel(const float* __restrict__ wptr,
                                                  float* __restrict__ out) {
    __shared__ float4 sg[96];
    __shared__ float2 spart[3][128];
    const int tid = threadIdx.x;
    if (tid < 96) sg[tid] = g_trig4[tid];
    __syncthreads();

    const int pxi   = tid & 127;
    const int slice = tid >> 7;              // 0..3
    const int p  = blockIdx.x * 128 + pxi;
    const int ix = p & (W - 1);
    const int iy = p >> 8;
    const float px = (float)ix - 127.5f;
    const float py = (float)iy - 127.5f;
    const float npx = -px;

    float accA0 = 0.f, accB0 = 0.f, accA1 = 0.f, accB1 = 0.f;
    const int v0 = slice * 24;
    const float4* __restrict__ row  = g_pair + v0 * D;          // angle v
    const float4* __restrict__ rowm = g_pair + (96 + v0) * D;   // angle v+96

    #pragma unroll 2
    for (int v = v0; v < v0 + 24; ++v, row += D, rowm += D) {
        const float4 q = sg[v];
        const float svDP = q.x, cvDP = q.y, svI = q.z, cvI = q.w;

        const float jc = fmaf(py, cvI, fmaf(npx, svI, 127.5f));
        const float kc = fmaf(px, cvI, fmaf(py,  svI, 127.5f));
        const float jf = floorf(jc), kf = floorf(kc);
        const float fj = jc - jf,    fk = kc - kf;
        const int   j0 = (int)jf;
        const int   k0 = (int)kf;

        const float dx00 = fmaf(fj, svDP, -(fk * cvDP));
        const float u    = fmaf(fj, cvDP,  (fk * svDP));
        const float dx10 = dx00 - svDP;
        const float dx01 = dx00 + cvDP;
        const float dx11 = dx10 + cvDP;
        const float e10  = u - cvDP;
        const float e01  = u - svDP;
        const float e11  = e10 - svDP;

        const float hx00 = __saturatef(1.f - fabsf(dx00));
        const float hx10 = __saturatef(1.f - fabsf(dx10));
        const float hx01 = __saturatef(1.f - fabsf(dx01));
        const float hx11 = __saturatef(1.f - fabsf(dx11));
        const float hy00 = __saturatef(1.f - fabsf(u));
        const float hy10 = __saturatef(1.f - fabsf(e10));
        const float hy01 = __saturatef(1.f - fabsf(e01));
        const float hy11 = __saturatef(1.f - fabsf(e11));

        const float P00 = hx00 * hy00;
        const float P10 = hx10 * hy10;
        const float P01 = hx01 * hy01;
        const float P11 = hx11 * hy11;

        const float q0 = P00 + P01, q1 = P10 + P11;   // angle v
        const float r0 = P01 + P11, r1 = P00 + P10;   // angle v+96

        const float4 t01 = __ldg(row + j0);
        const float4 m01 = __ldg(rowm + (254 - k0));
        accA0 = fmaf(t01.x, q0, fmaf(t01.z, q1, accA0));
        accB0 = fmaf(t01.y, q0, fmaf(t01.w, q1, accB0));
        accA1 = fmaf(m01.x, r0, fmaf(m01.z, r1, accA1));
        accB1 = fmaf(m01.y, r0, fmaf(m01.w, r1, accB1));
    }

    const float accA = accA0 + accA1;
    const float accB = accB0 + accB1;
    if (slice != 0) spart[slice - 1][pxi] = make_float2(accA, accB);
    __syncthreads();
    if (slice == 0) {
        float a = accA, b = accB;
        #pragma unroll
        for (int s = 0; s < 3; ++s) {       // fixed order -> deterministic
            float2 t = spart[s][pxi];
            a += t.x; b += t.y;
        }
        const float wdt = __ldg(wptr) * DTf;
        const float2 ia = g_img2[p];
        out[p]      = fmaf(-wdt, a, ia.x);
        out[p + HW] = fmaf(-wdt, b, ia.y);
    }
}

// ---------------------------------------------------------------------------
extern "C" void kernel_launch(void* const* d_in, const int* in_sizes, int n_in,
                              void* d_out, int out_size) {
    const float* img  = (const float*)d_in[0];   // [2,1,256,256]
    const float* proj = (const float*)d_in[1];   // [2,1,192,256]
    const float* wptr = (const float*)d_in[2];   // [1]
    float* out = (float*)d_out;                  // [2,1,256,256]

    prep_kernel<<<256, 256>>>(img);
    fwd2_kernel<<<768, 256>>>(proj);
    combine_kernel<<<192, 256>>>(proj);
    bwd_kernel<<<HW / 128, 512>>>(wptr, out);
}

// round 10
// speedup vs baseline: 1.8056x; 1.1216x over previous
#include <cuda_runtime.h>
#include <math.h>

#define H 256
#define W 256
#define V 192
#define D 256
#define S 256
#define HW (H*W)
#define PW 264              /* padded stride: data at [2,257], frame zeros [0,259] */

#define SQRT2_D 1.4142135623730951
#define DPf     ((float)(2.0 * SQRT2_D * 128.0 / 255.0))   /* sample spacing, px */
#define OFFf    ((float)(-SQRT2_D * 128.0))
#define INV_DPf ((float)(255.0 / (256.0 * SQRT2_D)))
#define DTf     ((float)(2.0 * SQRT2_D / 256.0))
#define PI_D    3.141592653589793

__device__ float4 g_pair4N[PW * PW]; // (A[y][x],B[y][x],A[y][x+1],B[y][x+1]) padded
__device__ float4 g_pair4T[PW * PW]; // transposed pairs: (A[y][x],B,A[y+1][x],B)
__device__ float2 g_img2 [HW];       // unpadded interleave (bwd final update)
__device__ float2 g_temp [V * D];    // residual sinogram rows v<96 (A,B)
__device__ float4 g_pair [V * D];    // (temp[j], temp[j+1]) x both images
__device__ float  g_colA [8 * 96 * 256];  // column partial sums, 8 row-groups
__device__ float  g_colB [8 * 96 * 256];
__device__ float4 g_trig4[96];       // {svDP, cvDP, svI, cvI} for bwd
__device__ float2 g_trigB[96];       // raw {cv, sv} for fwd2

// ---------------------------------------------------------------------------
// prep: build x-shifted pair images (normal + transposed) from a 17x17-halo
// smem tile (all global accesses coalesced), border-frame zeroing, trig.
// ---------------------------------------------------------------------------
__global__ void __launch_bounds__(256) prep_kernel(const float* __restrict__ img) {
    __shared__ float2 s[17][17];
    const int tid = threadIdx.x;
    const int tx = tid & 15, ty = tid >> 4;
    const int bx = (blockIdx.x & 15) << 4;
    const int by = (blockIdx.x >> 4) << 4;

    for (int i = tid; i < 289; i += 256) {
        int r = i / 17, c = i - r * 17;
        int y = by + r, x = bx + c;
        float2 val = make_float2(0.f, 0.f);
        if (x < W && y < H) val = make_float2(img[y * W + x], img[y * W + x + HW]);
        s[r][c] = val;
    }
    __syncthreads();

    {   // normal pair + unpadded interleave
        int x = bx + tx, y = by + ty;
        float2 v00 = s[ty][tx], v01 = s[ty][tx + 1];
        g_img2[y * W + x] = v00;
        g_pair4N[(y + 2) * PW + (x + 2)] = make_float4(v00.x, v00.y, v01.x, v01.y);
    }
    {   // transposed pair: out(row=x, col=y) = (img[y][x], img[y+1][x])
        float2 u0 = s[tx][ty], u1 = s[tx + 1][ty];
        g_pair4T[(bx + ty + 2) * PW + (by + tx + 2)] = make_float4(u0.x, u0.y, u1.x, u1.y);
    }

    // border frame zeroing: [0,259]^2 minus [2,257]^2 = 2064 cells per array
    if (blockIdx.x < 2) {
        float4* dst = (blockIdx.x == 0) ? g_pair4N : g_pair4T;
        for (int i = tid; i < 2064; i += 256) {
            int r, c;
            if (i < 1040) {                    // rows {0,1,258,259} x cols [0,259]
                int rr = i / 260;  c = i - rr * 260;
                r = (rr < 2) ? rr : (256 + rr);
            } else {                           // cols {0,1,258,259} x rows [2,257]
                int j = i - 1040;
                int cc = j / 256;  r = 2 + (j - cc * 256);
                c = (cc < 2) ? cc : (256 + cc);
            }
            dst[r * PW + c] = make_float4(0.f, 0.f, 0.f, 0.f);
        }
    }

    if (blockIdx.x < 96 && tid == 0) {
        const int v = blockIdx.x;
        float cv, sv;
        float af = (float)((double)v * (PI_D / 192.0));
        sincosf(af, &sv, &cv);
        g_trigB[v] = make_float2(cv, sv);
        g_trig4[v] = make_float4(sv * DPf, cv * DPf, sv * INV_DPf, cv * INV_DPf);
    }
}

// ---------------------------------------------------------------------------
// fwd2: sample field F_v[j][k] for base angles v<96 serves BOTH sinogram
// halves (90-degree identity): row-sum_k -> sino[v][j]; col-sum_j -> the
// reversed row sino[v+96]. Warp-per-row (lanes along k). Pair images give
// 2 LDG.128 per bilinear sample instead of 4 LDG.64.
// ---------------------------------------------------------------------------
__global__ void __launch_bounds__(256) fwd2_kernel(const float* __restrict__ proj) {
    __shared__ float2 shW[8][256];               // per-warp column partials
    const int bid = blockIdx.x;
    const int v   = bid >> 3;
    const int grp = bid & 7;
    const int tid = threadIdx.x;
    const int warp = tid >> 5, lane = tid & 31;

    const float2 tv = g_trigB[v];
    const float cv = tv.x, sv = tv.y;
    const bool steep = fabsf(sv) > fabsf(cv);
    const float4* __restrict__ im4 = steep ? g_pair4T : g_pair4N;
    const float c2 = steep ? sv : cv;
    const float s2 = steep ? cv : sv;

    float cA[8], cB[8];
    #pragma unroll
    for (int c = 0; c < 8; ++c) { cA[c] = 0.f; cB[c] = 0.f; }

    #pragma unroll 1
    for (int r = 0; r < 4; ++r) {
        const int j = (grp << 5) + (r << 3) + warp;
        const float s128 = fmaf((float)j, DPf, OFFf);
        const float ax0 = fmaf(-s128, sv, 129.5f);   // padded (+2)
        const float ay0 = fmaf( s128, cv, 129.5f);
        const float aX = steep ? ay0 : ax0;
        const float aY = steep ? ax0 : ay0;
        const float bX = fmaf(OFFf, c2, aX), sX = DPf * c2;   // X(k) = bX + k*sX
        const float bY = fmaf(OFFf, s2, aY), sY = DPf * s2;

        float lo = 0.f, hi = 255.f;
        bool empty = false;
        {
            float rr = 1.0f / sX;
            float t1 = (0.999f - bX) * rr, t2 = (258.001f - bX) * rr;
            lo = fmaxf(lo, fminf(t1, t2)); hi = fminf(hi, fmaxf(t1, t2));
        }
        if (fabsf(sY) > 1e-6f) {
            float rr = 1.0f / sY;
            float t1 = (0.999f - bY) * rr, t2 = (258.001f - bY) * rr;
            lo = fmaxf(lo, fminf(t1, t2)); hi = fminf(hi, fmaxf(t1, t2));
        } else if (bY < 0.999f || bY > 258.001f) empty = true;

        int klo = (int)ceilf(lo), khi = (int)floorf(hi);
        float rowA = 0.f, rowB = 0.f;
        if (!empty && klo <= khi) {
            const int c0 = klo >> 5, c1 = khi >> 5;
            #pragma unroll
            for (int c = 0; c < 8; ++c) {
                if (c >= c0 && c <= c1) {           // warp-uniform branch
                    const int k = (c << 5) + lane;
                    const float pred = (k >= klo && k <= khi) ? 1.f : 0.f;
                    float X = fmaf((float)k, sX, bX);
                    float Y = fmaf((float)k, sY, bY);
                    X = fminf(fmaxf(X, 0.f), 258.f);   // safe for pred=0 lanes
                    Y = fminf(fmaxf(Y, 0.f), 258.f);
                    float Xf = floorf(X), Yf = floorf(Y);
                    float fx = X - Xf, fy = Y - Yf;
                    int base = (int)Yf * PW + (int)Xf;
                    float4 t0 = __ldg(im4 + base);        // (A00,B00,A10,B10)
                    float4 t1 = __ldg(im4 + base + PW);   // (A01,B01,A11,B11)
                    float gx = 1.f - fx, gy = 1.f - fy;
                    float w00 = gx * gy, w10 = fx * gy, w01 = gx * fy, w11 = fx * fy;
                    float fa = fmaf(t0.x, w00, fmaf(t0.z, w10, fmaf(t1.x, w01, t1.z * w11)));
                    float fb = fmaf(t0.y, w00, fmaf(t0.w, w10, fmaf(t1.y, w01, t1.w * w11)));
                    fa *= pred; fb *= pred;
                    rowA += fa;  rowB += fb;
                    cA[c] += fa; cB[c] += fb;
                }
            }
        }
        #pragma unroll
        for (int o = 16; o; o >>= 1) {
            rowA += __shfl_xor_sync(0xffffffffu, rowA, o);
            rowB += __shfl_xor_sync(0xffffffffu, rowB, o);
        }
        if (lane == 0) {
            int idx = v * D + j;
            g_temp[idx] = make_float2(fmaf(DTf, rowA, -__ldg(proj + idx)),
                                      fmaf(DTf, rowB, -__ldg(proj + idx + V * D)));
        }
    }

    // deterministic column reduction: warp slices -> smem -> fixed-order sum
    #pragma unroll
    for (int c = 0; c < 8; ++c)
        shW[warp][(c << 5) + lane] = make_float2(cA[c], cB[c]);
    __syncthreads();
    float a = 0.f, b = 0.f;
    #pragma unroll
    for (int w = 0; w < 8; ++w) {
        float2 t = shW[w][tid];
        a += t.x; b += t.y;
    }
    g_colA[((grp * 96 + v) << 8) + tid] = a;
    g_colB[((grp * 96 + v) << 8) + tid] = b;
}

// ---------------------------------------------------------------------------
// combine: finalize sinogram rows v>=96 (fixed-order, deterministic) and
// build the float4 pair array (t[j], t[j+1]) for bwd.
// ---------------------------------------------------------------------------
__global__ void __launch_bounds__(256) combine_kernel(const float* __restrict__ proj) {
    __shared__ float2 sval[256];
    const int v = blockIdx.x;          // 0..191
    const int j = threadIdx.x;
    float2 val;
    if (v < 96) {
        val = g_temp[v * D + j];
    } else {
        const int vb = v - 96;
        const int kk = 255 - j;
        float a = 0.f, b = 0.f;
        #pragma unroll
        for (int g = 0; g < 8; ++g) {
            a += g_colA[((g * 96 + vb) << 8) + kk];
            b += g_colB[((g * 96 + vb) << 8) + kk];
        }
        int idx = v * D + j;
        val = make_float2(fmaf(DTf, a, -__ldg(proj + idx)),
                          fmaf(DTf, b, -__ldg(proj + idx + V * D)));
    }
    sval[j] = val;
    __syncthreads();
    float2 nxt = sval[min(j + 1, 255)];
    g_pair[(v << 8) + j] = make_float4(val.x, val.y, nxt.x, nxt.y);
}

// ---------------------------------------------------------------------------
// backprojection + update. 512-thread blocks: 4 angle-slices x 128 pixels;
// fixed-order smem combine (deterministic).
// ---------------------------------------------------------------------------
__global__ void __launch_bounds__(512) bwd_kernel(const float* __restrict__ wptr,
                                                  float* __restrict__ out) {
    __shared__ float4 sg[96];
    __shared__ float2 spart[3][128];
    const int tid = threadIdx.x;
    if (tid < 96) sg[tid] = g_trig4[tid];
    __syncthreads();

    const int pxi   = tid & 127;
    const int slice = tid >> 7;              // 0..3
    const int p  = blockIdx.x * 128 + pxi;
    const int ix = p & (W - 1);
    const int iy = p >> 8;
    const float px = (float)ix - 127.5f;
    const float py = (float)iy - 127.5f;
    const float npx = -px;

    float accA0 = 0.f, accB0 = 0.f, accA1 = 0.f, accB1 = 0.f;
    const int v0 = slice * 24;
    const float4* __restrict__ row  = g_pair + v0 * D;          // angle v
    const float4* __restrict__ rowm = g_pair + (96 + v0) * D;   // angle v+96

    #pragma unroll 2
    for (int v = v0; v < v0 + 24; ++v, row += D, rowm += D) {
        const float4 q = sg[v];
        const float svDP = q.x, cvDP = q.y, svI = q.z, cvI = q.w;

        const float jc = fmaf(py, cvI, fmaf(npx, svI, 127.5f));
        const float kc = fmaf(px, cvI, fmaf(py,  svI, 127.5f));
        const float jf = floorf(jc), kf = floorf(kc);
        const float fj = jc - jf,    fk = kc - kf;
        const int   j0 = (int)jf;
        const int   k0 = (int)kf;

        const float dx00 = fmaf(fj, svDP, -(fk * cvDP));
        const float u    = fmaf(fj, cvDP,  (fk * svDP));
        const float dx10 = dx00 - svDP;
        const float dx01 = dx00 + cvDP;
        const float dx11 = dx10 + cvDP;
        const float e10  = u - cvDP;
        const float e01  = u - svDP;
        const float e11  = e10 - svDP;

        const float hx00 = __saturatef(1.f - fabsf(dx00));
        const float hx10 = __saturatef(1.f - fabsf(dx10));
        const float hx01 = __saturatef(1.f - fabsf(dx01));
        const float hx11 = __saturatef(1.f - fabsf(dx11));
        const float hy00 = __saturatef(1.f - fabsf(u));
        const float hy10 = __saturatef(1.f - fabsf(e10));
        const float hy01 = __saturatef(1.f - fabsf(e01));
        const float hy11 = __saturatef(1.f - fabsf(e11));

        const float P00 = hx00 * hy00;
        const float P10 = hx10 * hy10;
        const float P01 = hx01 * hy01;
        const float P11 = hx11 * hy11;

        const float q0 = P00 + P01, q1 = P10 + P11;   // angle v
        const float r0 = P01 + P11, r1 = P00 + P10;   // angle v+96

        const float4 t01 = __ldg(row + j0);
        const float4 m01 = __ldg(rowm + (254 - k0));
        accA0 = fmaf(t01.x, q0, fmaf(t01.z, q1, accA0));
        accB0 = fmaf(t01.y, q0, fmaf(t01.w, q1, accB0));
        accA1 = fmaf(m01.x, r0, fmaf(m01.z, r1, accA1));
        accB1 = fmaf(m01.y, r0, fmaf(m01.w, r1, accB1));
    }

    const float accA = accA0 + accA1;
    const float accB = accB0 + accB1;
    if (slice != 0) spart[slice - 1][pxi] = make_float2(accA, accB);
    __syncthreads();
    if (slice == 0) {
        float a = accA, b = accB;
        #pragma unroll
        for (int s = 0; s < 3; ++s) {       // fixed order -> deterministic
            float2 t = spart[s][pxi];
            a += t.x; b += t.y;
        }
        const float wdt = __ldg(wptr) * DTf;
        const float2 ia = g_img2[p];
        out[p]      = fmaf(-wdt, a, ia.x);
        out[p + HW] = fmaf(-wdt, b, ia.y);
    }
}

// ---------------------------------------------------------------------------
extern "C" void kernel_launch(void* const* d_in, const int* in_sizes, int n_in,
                              void* d_out, int out_size) {
    const float* img  = (const float*)d_in[0];   // [2,1,256,256]
    const float* proj = (const float*)d_in[1];   // [2,1,192,256]
    const float* wptr = (const float*)d_in[2];   // [1]
    float* out = (float*)d_out;                  // [2,1,256,256]

    prep_kernel<<<256, 256>>>(img);
    fwd2_kernel<<<768, 256>>>(proj);
    combine_kernel<<<192, 256>>>(proj);
    bwd_kernel<<<HW / 128, 512>>>(wptr, out);
}